// round 2
// baseline (speedup 1.0000x reference)
#include <cuda_runtime.h>
#include <cuda_bf16.h>
#include <math.h>

#define NN 100000
#define NE 1600000
#define NG 100
#define NH 8
#define NC 16
#define NF 128

// ---------------- scratch (static device globals; no runtime allocation) ----
__device__ float g_h[(size_t)NN * NF];       // 51.2 MB  projected features
__device__ float g_asrc[NN * NH];
__device__ float g_adst[NN * NH];
__device__ float g_s[NN * NH];               // softmax denominators
__device__ float g_acc[NN * NC];             // head-averaged message accum
__device__ float g_colsum[NF];
__device__ float g_colsq[NF];
__device__ float g_scale[NF];
__device__ float g_shift[NF];
__device__ float g_pool[NG * NC];
__device__ float g_cnt[NG];

// ---------------- K0: zero accumulators ------------------------------------
__global__ void k_zero() {
    int i = blockIdx.x * blockDim.x + threadIdx.x;
    int st = gridDim.x * blockDim.x;
    for (int k = i; k < NN * NC; k += st) g_acc[k] = 0.f;
    if (i < NF) { g_colsum[i] = 0.f; g_colsq[i] = 0.f; }
    if (i < NG * NC) g_pool[i] = 0.f;
    if (i < NG) g_cnt[i] = 0.f;
}

// ---------------- K1: BN column stats --------------------------------------
__global__ void k_stats(const float* __restrict__ x) {
    __shared__ float ssum[NF];
    __shared__ float ssq[NF];
    int t = threadIdx.x;            // 256 threads = 8 warps
    int lane = t & 31;
    int warp = t >> 5;
    int col = lane * 4;
    if (t < NF) { ssum[t] = 0.f; ssq[t] = 0.f; }
    __syncthreads();

    float s0 = 0.f, s1 = 0.f, s2 = 0.f, s3 = 0.f;
    float q0 = 0.f, q1 = 0.f, q2 = 0.f, q3 = 0.f;
    int row = blockIdx.x * 8 + warp;
    int step = gridDim.x * 8;
    for (int r = row; r < NN; r += step) {
        float4 v = *(const float4*)(x + (size_t)r * NF + col);
        s0 += v.x; s1 += v.y; s2 += v.z; s3 += v.w;
        q0 += v.x * v.x; q1 += v.y * v.y; q2 += v.z * v.z; q3 += v.w * v.w;
    }
    atomicAdd(&ssum[col + 0], s0); atomicAdd(&ssum[col + 1], s1);
    atomicAdd(&ssum[col + 2], s2); atomicAdd(&ssum[col + 3], s3);
    atomicAdd(&ssq[col + 0], q0);  atomicAdd(&ssq[col + 1], q1);
    atomicAdd(&ssq[col + 2], q2);  atomicAdd(&ssq[col + 3], q3);
    __syncthreads();
    if (t < NF) {
        atomicAdd(&g_colsum[t], ssum[t]);
        atomicAdd(&g_colsq[t], ssq[t]);
    }
}

// ---------------- K2: finalize BN scale/shift ------------------------------
__global__ void k_bnfin(const float* __restrict__ gamma, const float* __restrict__ beta) {
    int t = threadIdx.x;
    if (t < NF) {
        float mean = g_colsum[t] * (1.f / NN);
        float var = g_colsq[t] * (1.f / NN) - mean * mean;
        float sc = gamma[t] * rsqrtf(var + 1e-5f);
        g_scale[t] = sc;
        g_shift[t] = beta[t] - mean * sc;
    }
}

// ---------------- K3: fused BN-normalize + GEMM + attention logits ---------
// 128 nodes per block, 256 threads, 8x8 microtile per thread.
#define GEMM_SMEM_FLOATS (128 * 132 + 128 * 128 + 256)
#define GEMM_SMEM_BYTES (GEMM_SMEM_FLOATS * 4)

__global__ void __launch_bounds__(256, 1)
k_gemm(const float* __restrict__ x, const float* __restrict__ W,
       const float* __restrict__ attS, const float* __restrict__ attD) {
    extern __shared__ float sm[];
    float* sxT = sm;                       // [128][132]
    float* sw = sm + 128 * 132;            // [128][128]
    float* sAS = sw + 128 * 128;           // [128]
    float* sAD = sAS + 128;                // [128]

    int t = threadIdx.x;
    int r0 = blockIdx.x * 128;

    // load W (row-major [k][j])
    for (int i = t; i < (128 * 128) / 4; i += 256)
        ((float4*)sw)[i] = ((const float4*)W)[i];
    if (t < 128) { sAS[t] = attS[t]; sAD[t] = attD[t]; }

    // load + normalize + transpose x tile
    for (int i = t; i < 128 * 128; i += 256) {
        int row = i >> 7, col = i & 127;
        int n = r0 + row;
        float v = 0.f;
        if (n < NN) v = x[(size_t)n * NF + col] * g_scale[col] + g_shift[col];
        sxT[col * 132 + row] = v;
    }
    __syncthreads();

    int j = t & 15, i4 = t >> 4;
    float acc[8][8];
#pragma unroll
    for (int m = 0; m < 8; ++m)
#pragma unroll
        for (int n = 0; n < 8; ++n) acc[m][n] = 0.f;

    const float* aBase = sxT + i4 * 8;
    const float* bBase = sw + j * 8;
#pragma unroll 4
    for (int k = 0; k < 128; ++k) {
        float4 a0 = *(const float4*)(aBase + k * 132);
        float4 a1 = *(const float4*)(aBase + k * 132 + 4);
        float4 b0 = *(const float4*)(bBase + k * 128);
        float4 b1 = *(const float4*)(bBase + k * 128 + 4);
        float a[8] = {a0.x, a0.y, a0.z, a0.w, a1.x, a1.y, a1.z, a1.w};
        float b[8] = {b0.x, b0.y, b0.z, b0.w, b1.x, b1.y, b1.z, b1.w};
#pragma unroll
        for (int m = 0; m < 8; ++m)
#pragma unroll
            for (int n = 0; n < 8; ++n) acc[m][n] = fmaf(a[m], b[n], acc[m][n]);
    }
    __syncthreads();

    // stage h tile into smem (reuse sw)
    float* sh = sw;
#pragma unroll
    for (int m = 0; m < 8; ++m) {
        float4 v0 = make_float4(acc[m][0], acc[m][1], acc[m][2], acc[m][3]);
        float4 v1 = make_float4(acc[m][4], acc[m][5], acc[m][6], acc[m][7]);
        *(float4*)(sh + (i4 * 8 + m) * 128 + j * 8) = v0;
        *(float4*)(sh + (i4 * 8 + m) * 128 + j * 8 + 4) = v1;
    }
    __syncthreads();

    int rowsValid = NN - r0;
    if (rowsValid > 128) rowsValid = 128;

    // write h tile to global (coalesced float4)
    for (int i = t; i < 128 * 32; i += 256) {
        int row = i >> 5, c4 = i & 31;
        if (row < rowsValid)
            ((float4*)(g_h + (size_t)(r0 + row) * NF))[c4] = ((const float4*)(sh + row * 128))[c4];
    }

    // attention logits + self-loop softmax seed
    int node = t >> 1, half = t & 1;
    if (node < rowsValid) {
        int n = r0 + node;
        for (int hh = half * 4; hh < half * 4 + 4; ++hh) {
            const float* hr = sh + node * 128 + hh * 16;
            float as = 0.f, ad = 0.f;
#pragma unroll
            for (int c = 0; c < 16; ++c) {
                as = fmaf(hr[c], sAS[hh * 16 + c], as);
                ad = fmaf(hr[c], sAD[hh * 16 + c], ad);
            }
            g_asrc[n * NH + hh] = as;
            g_adst[n * NH + hh] = ad;
            float e = as + ad;
            e = e > 0.f ? e : 0.2f * e;
            g_s[n * NH + hh] = __expf(e);   // self-loop contribution
        }
    }
}

// ---------------- K4: edge pass 1 — softmax denominators -------------------
__device__ __forceinline__ float lrelu_exp(float a, float b) {
    float e = a + b;
    e = e > 0.f ? e : 0.2f * e;
    return __expf(e);
}

__global__ void k_edge_s(const int* __restrict__ ei) {
    int e = blockIdx.x * blockDim.x + threadIdx.x;
    if (e >= NE) return;
    int s = ei[e];
    int d = ei[NE + e];
    float4 a0 = *(const float4*)(g_asrc + s * NH);
    float4 a1 = *(const float4*)(g_asrc + s * NH + 4);
    float4 b0 = *(const float4*)(g_adst + d * NH);
    float4 b1 = *(const float4*)(g_adst + d * NH + 4);
    float w0 = lrelu_exp(a0.x, b0.x), w1 = lrelu_exp(a0.y, b0.y);
    float w2 = lrelu_exp(a0.z, b0.z), w3 = lrelu_exp(a0.w, b0.w);
    float w4 = lrelu_exp(a1.x, b1.x), w5 = lrelu_exp(a1.y, b1.y);
    float w6 = lrelu_exp(a1.z, b1.z), w7 = lrelu_exp(a1.w, b1.w);
    float* sp = g_s + d * NH;
    atomicAdd(sp + 0, w0); atomicAdd(sp + 1, w1);
    atomicAdd(sp + 2, w2); atomicAdd(sp + 3, w3);
    atomicAdd(sp + 4, w4); atomicAdd(sp + 5, w5);
    atomicAdd(sp + 6, w6); atomicAdd(sp + 7, w7);
}

// ---------------- K5: edge pass 2 — head-averaged message scatter ----------
// 4 threads per edge; lane q handles channels [4q, 4q+4).
__global__ void k_edge_msg(const int* __restrict__ ei) {
    int gt = blockIdx.x * blockDim.x + threadIdx.x;
    int e = gt >> 2, q = gt & 3;
    if (e >= NE) return;
    int s = ei[e];
    int d = ei[NE + e];
    float4 a0 = *(const float4*)(g_asrc + s * NH);
    float4 a1 = *(const float4*)(g_asrc + s * NH + 4);
    float4 b0 = *(const float4*)(g_adst + d * NH);
    float4 b1 = *(const float4*)(g_adst + d * NH + 4);
    float4 s0 = *(const float4*)(g_s + d * NH);
    float4 s1 = *(const float4*)(g_s + d * NH + 4);
    float al[8];
    al[0] = 0.125f * __fdividef(lrelu_exp(a0.x, b0.x), s0.x);
    al[1] = 0.125f * __fdividef(lrelu_exp(a0.y, b0.y), s0.y);
    al[2] = 0.125f * __fdividef(lrelu_exp(a0.z, b0.z), s0.z);
    al[3] = 0.125f * __fdividef(lrelu_exp(a0.w, b0.w), s0.w);
    al[4] = 0.125f * __fdividef(lrelu_exp(a1.x, b1.x), s1.x);
    al[5] = 0.125f * __fdividef(lrelu_exp(a1.y, b1.y), s1.y);
    al[6] = 0.125f * __fdividef(lrelu_exp(a1.z, b1.z), s1.z);
    al[7] = 0.125f * __fdividef(lrelu_exp(a1.w, b1.w), s1.w);

    const float* hrow = g_h + (size_t)s * NF + q * 4;
    float r0 = 0.f, r1 = 0.f, r2 = 0.f, r3 = 0.f;
#pragma unroll
    for (int h = 0; h < NH; ++h) {
        float4 hv = *(const float4*)(hrow + h * 16);
        r0 = fmaf(al[h], hv.x, r0);
        r1 = fmaf(al[h], hv.y, r1);
        r2 = fmaf(al[h], hv.z, r2);
        r3 = fmaf(al[h], hv.w, r3);
    }
    float* op = g_acc + d * NC + q * 4;
    atomicAdd(op + 0, r0); atomicAdd(op + 1, r1);
    atomicAdd(op + 2, r2); atomicAdd(op + 3, r3);
}

// ---------------- K6: node finalize (self-loop msg + bias + ELU + pool) ----
__global__ void k_node_final(const int* __restrict__ batch,
                             const float* __restrict__ bias) {
    int gt = blockIdx.x * blockDim.x + threadIdx.x;
    int n = gt >> 4, c = gt & 15;
    if (n >= NN) return;
    float v = g_acc[n * NC + c];
    const float* hr = g_h + (size_t)n * NF;
#pragma unroll
    for (int h = 0; h < NH; ++h) {
        float a = g_asrc[n * NH + h] + g_adst[n * NH + h];
        a = a > 0.f ? a : 0.2f * a;
        float w = __fdividef(__expf(a), g_s[n * NH + h]);
        v = fmaf(0.125f * w, hr[h * 16 + c], v);
    }
    v += bias[c];
    v = v > 0.f ? v : expm1f(v);
    int b = batch[n];
    atomicAdd(&g_pool[b * NC + c], v);
    if (c == 0) atomicAdd(&g_cnt[b], 1.0f);
}

// ---------------- K7: pooled mean ------------------------------------------
__global__ void k_pool_div(float* __restrict__ out) {
    int i = blockIdx.x * blockDim.x + threadIdx.x;
    if (i < NG * NC) {
        int g = i >> 4;
        out[i] = g_pool[i] / fmaxf(g_cnt[g], 1.0f);
    }
}

// ---------------- launch ----------------------------------------------------
extern "C" void kernel_launch(void* const* d_in, const int* in_sizes, int n_in,
                              void* d_out, int out_size) {
    const float* x = (const float*)d_in[0];
    const int* ei = (const int*)d_in[1];
    const int* batch = (const int*)d_in[2];
    const float* gamma = (const float*)d_in[3];
    const float* beta = (const float*)d_in[4];
    const float* W = (const float*)d_in[5];
    const float* attS = (const float*)d_in[6];
    const float* attD = (const float*)d_in[7];
    const float* bias = (const float*)d_in[8];
    float* out = (float*)d_out;

    cudaFuncSetAttribute(k_gemm, cudaFuncAttributeMaxDynamicSharedMemorySize,
                         GEMM_SMEM_BYTES);

    k_zero<<<256, 256>>>();
    k_stats<<<512, 256>>>(x);
    k_bnfin<<<1, 128>>>(gamma, beta);
    k_gemm<<<(NN + 127) / 128, 256, GEMM_SMEM_BYTES>>>(x, W, attS, attD);
    k_edge_s<<<(NE + 255) / 256, 256>>>(ei);
    k_edge_msg<<<(NE * 4 + 255) / 256, 256>>>(ei);
    k_node_final<<<(NN * 16 + 255) / 256, 256>>>(batch, bias);
    k_pool_div<<<(NG * NC + 255) / 256, 256>>>(out);
}

// round 4
// speedup vs baseline: 1.3045x; 1.3045x over previous
#include <cuda_runtime.h>
#include <cuda_bf16.h>
#include <math.h>

#define NN 100000
#define NE 1600000
#define NG 100
#define NH 8
#define NC 16
#define NF 128

// ---------------- scratch (static device globals) ---------------------------
__device__ __align__(16) float g_h[(size_t)NN * NF];   // 51.2 MB projected features
__device__ __align__(16) float g_asrc[NN * NH];
__device__ __align__(16) float g_adst[NN * NH];
__device__ __align__(16) float g_s[NN * NH];           // softmax denom, then inverted
__device__ __align__(16) float g_acc[NN * NC];         // head-averaged message accum
__device__ __align__(16) float g_colsum[NF];
__device__ __align__(16) float g_colsq[NF];
__device__ __align__(16) float g_scale[NF];
__device__ __align__(16) float g_shift[NF];
__device__ __align__(16) float g_pool[NG * NC];
__device__ __align__(16) float g_cnt[NG];

// vector reduction (no return) --------------------------------------------
__device__ __forceinline__ void red_v4(float* p, float a, float b, float c, float d) {
    asm volatile("red.global.add.v4.f32 [%0], {%1, %2, %3, %4};"
                 :: "l"(p), "f"(a), "f"(b), "f"(c), "f"(d) : "memory");
}

// ---------------- K0: zero accumulators ------------------------------------
__global__ void k_zero() {
    int i = blockIdx.x * blockDim.x + threadIdx.x;
    int st = gridDim.x * blockDim.x;
    for (int k = i; k < NN * NC; k += st) g_acc[k] = 0.f;
    if (i < NF) { g_colsum[i] = 0.f; g_colsq[i] = 0.f; }
    if (i < NG * NC) g_pool[i] = 0.f;
    if (i < NG) g_cnt[i] = 0.f;
}

// ---------------- K1: BN column stats --------------------------------------
__global__ void k_stats(const float* __restrict__ x) {
    __shared__ float ssum[NF];
    __shared__ float ssq[NF];
    int t = threadIdx.x;
    int lane = t & 31;
    int warp = t >> 5;
    int col = lane * 4;
    if (t < NF) { ssum[t] = 0.f; ssq[t] = 0.f; }
    __syncthreads();

    float s0 = 0.f, s1 = 0.f, s2 = 0.f, s3 = 0.f;
    float q0 = 0.f, q1 = 0.f, q2 = 0.f, q3 = 0.f;
    int row = blockIdx.x * 8 + warp;
    int step = gridDim.x * 8;
    for (int r = row; r < NN; r += step) {
        float4 v = *(const float4*)(x + (size_t)r * NF + col);
        s0 += v.x; s1 += v.y; s2 += v.z; s3 += v.w;
        q0 += v.x * v.x; q1 += v.y * v.y; q2 += v.z * v.z; q3 += v.w * v.w;
    }
    atomicAdd(&ssum[col + 0], s0); atomicAdd(&ssum[col + 1], s1);
    atomicAdd(&ssum[col + 2], s2); atomicAdd(&ssum[col + 3], s3);
    atomicAdd(&ssq[col + 0], q0);  atomicAdd(&ssq[col + 1], q1);
    atomicAdd(&ssq[col + 2], q2);  atomicAdd(&ssq[col + 3], q3);
    __syncthreads();
    if (t < NF) {
        atomicAdd(&g_colsum[t], ssum[t]);
        atomicAdd(&g_colsq[t], ssq[t]);
    }
}

// ---------------- K2: finalize BN scale/shift ------------------------------
__global__ void k_bnfin(const float* __restrict__ gamma, const float* __restrict__ beta) {
    int t = threadIdx.x;
    if (t < NF) {
        float mean = g_colsum[t] * (1.f / NN);
        float var = g_colsq[t] * (1.f / NN) - mean * mean;
        float sc = gamma[t] * rsqrtf(var + 1e-5f);
        g_scale[t] = sc;
        g_shift[t] = beta[t] - mean * sc;
    }
}

// ---------------- K3: fused BN + GEMM + attention logits --------------------
// 128 nodes/block, 256 threads, 8x8 microtile; K chunked by 64 so two CTAs
// co-reside per SM. h stored straight from registers; logits via shfl pair.
#define KCH 64
#define SXT_STRIDE 132                           // bytes/row = 528 = 33*16 (16B aligned)
#define SXT_FLOATS (KCH * SXT_STRIDE)            // 8448
#define SW_FLOATS (KCH * 128)                    // 8192
#define GEMM_SMEM_BYTES ((SXT_FLOATS + SW_FLOATS) * 4)

__global__ void __launch_bounds__(256, 2)
k_gemm(const float* __restrict__ x, const float* __restrict__ W,
       const float* __restrict__ attS, const float* __restrict__ attD) {
    extern __shared__ float sm[];
    float* sxT = sm;                 // [k][row] stride 132
    float* sw = sm + SXT_FLOATS;     // [k][col]

    int t = threadIdx.x;
    int r0 = blockIdx.x * 128;
    int j = t & 15, i4 = t >> 4;

    float acc[8][8];
#pragma unroll
    for (int m = 0; m < 8; ++m)
#pragma unroll
        for (int n = 0; n < 8; ++n) acc[m][n] = 0.f;

    for (int k0 = 0; k0 < NF; k0 += KCH) {
        // load W chunk [KCH][128]
        for (int i = t; i < SW_FLOATS / 4; i += 256)
            ((float4*)sw)[i] = ((const float4*)(W + (size_t)k0 * 128))[i];
        // load + normalize + transpose x chunk
        for (int i = t; i < 128 * KCH; i += 256) {
            int row = i >> 6, col = i & 63;
            int n = r0 + row;
            float v = 0.f;
            if (n < NN) v = x[(size_t)n * NF + k0 + col] * g_scale[k0 + col] + g_shift[k0 + col];
            sxT[col * SXT_STRIDE + row] = v;
        }
        __syncthreads();

        const float* aBase = sxT + i4 * 8;
        const float* bBase = sw + j * 8;
#pragma unroll 4
        for (int k = 0; k < KCH; ++k) {
            float4 a0 = *(const float4*)(aBase + k * SXT_STRIDE);
            float4 a1 = *(const float4*)(aBase + k * SXT_STRIDE + 4);
            float4 b0 = *(const float4*)(bBase + k * 128);
            float4 b1 = *(const float4*)(bBase + k * 128 + 4);
            float a[8] = {a0.x, a0.y, a0.z, a0.w, a1.x, a1.y, a1.z, a1.w};
            float b[8] = {b0.x, b0.y, b0.z, b0.w, b1.x, b1.y, b1.z, b1.w};
#pragma unroll
            for (int m = 0; m < 8; ++m)
#pragma unroll
                for (int n = 0; n < 8; ++n) acc[m][n] = fmaf(a[m], b[n], acc[m][n]);
        }
        __syncthreads();
    }

    int rowsValid = NN - r0;
    if (rowsValid > 128) rowsValid = 128;

    // store h tile straight from registers (coalesced across j)
#pragma unroll
    for (int m = 0; m < 8; ++m) {
        int row = i4 * 8 + m;
        if (row < rowsValid) {
            float* hp = g_h + (size_t)(r0 + row) * NF + j * 8;
            *(float4*)hp = make_float4(acc[m][0], acc[m][1], acc[m][2], acc[m][3]);
            *(float4*)(hp + 4) = make_float4(acc[m][4], acc[m][5], acc[m][6], acc[m][7]);
        }
    }

    // attention logits: thread covers cols [j*8, j*8+8) = half of head hh=j>>1
    int hh = j >> 1;
    float asv[8], adv[8];
#pragma unroll
    for (int c = 0; c < 8; ++c) {
        asv[c] = attS[hh * 16 + (j & 1) * 8 + c];
        adv[c] = attD[hh * 16 + (j & 1) * 8 + c];
    }
#pragma unroll
    for (int m = 0; m < 8; ++m) {
        float ps = 0.f, pd = 0.f;
#pragma unroll
        for (int c = 0; c < 8; ++c) {
            ps = fmaf(acc[m][c], asv[c], ps);
            pd = fmaf(acc[m][c], adv[c], pd);
        }
        ps += __shfl_xor_sync(0xffffffffu, ps, 1);
        pd += __shfl_xor_sync(0xffffffffu, pd, 1);
        int row = i4 * 8 + m;
        if ((j & 1) == 0 && row < rowsValid) {
            int n = r0 + row;
            g_asrc[n * NH + hh] = ps;
            g_adst[n * NH + hh] = pd;
            float e = ps + pd;
            e = e > 0.f ? e : 0.2f * e;
            g_s[n * NH + hh] = __expf(e);   // self-loop contribution
        }
    }
}

// ---------------- K4: edge pass 1 — softmax denominators -------------------
__device__ __forceinline__ float lrelu_exp(float a, float b) {
    float e = a + b;
    e = e > 0.f ? e : 0.2f * e;
    return __expf(e);
}

__global__ void k_edge_s(const int* __restrict__ ei) {
    int e = blockIdx.x * blockDim.x + threadIdx.x;
    if (e >= NE) return;
    int s = ei[e];
    int d = ei[NE + e];
    float4 a0 = *(const float4*)(g_asrc + s * NH);
    float4 a1 = *(const float4*)(g_asrc + s * NH + 4);
    float4 b0 = *(const float4*)(g_adst + d * NH);
    float4 b1 = *(const float4*)(g_adst + d * NH + 4);
    float* sp = g_s + d * NH;
    red_v4(sp, lrelu_exp(a0.x, b0.x), lrelu_exp(a0.y, b0.y),
               lrelu_exp(a0.z, b0.z), lrelu_exp(a0.w, b0.w));
    red_v4(sp + 4, lrelu_exp(a1.x, b1.x), lrelu_exp(a1.y, b1.y),
                   lrelu_exp(a1.z, b1.z), lrelu_exp(a1.w, b1.w));
}

// ---------------- K4b: invert denominators ---------------------------------
__global__ void k_sinv() {
    int i = blockIdx.x * blockDim.x + threadIdx.x;
    if (i < NN * NH) g_s[i] = __frcp_rn(g_s[i]);
}

// ---------------- K5: edge pass 2 — head-averaged message scatter ----------
// 4 threads per edge; lane q handles channels [4q, 4q+4).
__global__ void k_edge_msg(const int* __restrict__ ei) {
    int gt = blockIdx.x * blockDim.x + threadIdx.x;
    int e = gt >> 2, q = gt & 3;
    if (e >= NE) return;
    int s = ei[e];
    int d = ei[NE + e];
    float4 a0 = *(const float4*)(g_asrc + s * NH);
    float4 a1 = *(const float4*)(g_asrc + s * NH + 4);
    float4 b0 = *(const float4*)(g_adst + d * NH);
    float4 b1 = *(const float4*)(g_adst + d * NH + 4);
    float4 s0 = *(const float4*)(g_s + d * NH);
    float4 s1 = *(const float4*)(g_s + d * NH + 4);
    float al[8];
    al[0] = 0.125f * lrelu_exp(a0.x, b0.x) * s0.x;
    al[1] = 0.125f * lrelu_exp(a0.y, b0.y) * s0.y;
    al[2] = 0.125f * lrelu_exp(a0.z, b0.z) * s0.z;
    al[3] = 0.125f * lrelu_exp(a0.w, b0.w) * s0.w;
    al[4] = 0.125f * lrelu_exp(a1.x, b1.x) * s1.x;
    al[5] = 0.125f * lrelu_exp(a1.y, b1.y) * s1.y;
    al[6] = 0.125f * lrelu_exp(a1.z, b1.z) * s1.z;
    al[7] = 0.125f * lrelu_exp(a1.w, b1.w) * s1.w;

    const float* hrow = g_h + (size_t)s * NF + q * 4;
    float r0 = 0.f, r1 = 0.f, r2 = 0.f, r3 = 0.f;
#pragma unroll
    for (int h = 0; h < NH; ++h) {
        float4 hv = *(const float4*)(hrow + h * 16);
        r0 = fmaf(al[h], hv.x, r0);
        r1 = fmaf(al[h], hv.y, r1);
        r2 = fmaf(al[h], hv.z, r2);
        r3 = fmaf(al[h], hv.w, r3);
    }
    red_v4(g_acc + d * NC + q * 4, r0, r1, r2, r3);
}

// ---------------- K6: node finalize (self-loop + bias + ELU + pool) --------
__global__ void k_node_final(const int* __restrict__ batch,
                             const float* __restrict__ bias) {
    int gt = blockIdx.x * blockDim.x + threadIdx.x;
    int n = gt >> 4, c = gt & 15;
    if (n >= NN) return;
    float v = g_acc[n * NC + c];
    const float* hr = g_h + (size_t)n * NF;
#pragma unroll
    for (int h = 0; h < NH; ++h) {
        float a = g_asrc[n * NH + h] + g_adst[n * NH + h];
        a = a > 0.f ? a : 0.2f * a;
        float w = __expf(a) * g_s[n * NH + h];   // g_s holds 1/s
        v = fmaf(0.125f * w, hr[h * 16 + c], v);
    }
    v += bias[c];
    v = v > 0.f ? v : expm1f(v);
    int b = batch[n];
    atomicAdd(&g_pool[b * NC + c], v);
    if (c == 0) atomicAdd(&g_cnt[b], 1.0f);
}

// ---------------- K7: pooled mean ------------------------------------------
__global__ void k_pool_div(float* __restrict__ out) {
    int i = blockIdx.x * blockDim.x + threadIdx.x;
    if (i < NG * NC) {
        int g = i >> 4;
        out[i] = g_pool[i] / fmaxf(g_cnt[g], 1.0f);
    }
}

// ---------------- launch ----------------------------------------------------
extern "C" void kernel_launch(void* const* d_in, const int* in_sizes, int n_in,
                              void* d_out, int out_size) {
    const float* x = (const float*)d_in[0];
    const int* ei = (const int*)d_in[1];
    const int* batch = (const int*)d_in[2];
    const float* gamma = (const float*)d_in[3];
    const float* beta = (const float*)d_in[4];
    const float* W = (const float*)d_in[5];
    const float* attS = (const float*)d_in[6];
    const float* attD = (const float*)d_in[7];
    const float* bias = (const float*)d_in[8];
    float* out = (float*)d_out;

    cudaFuncSetAttribute(k_gemm, cudaFuncAttributeMaxDynamicSharedMemorySize,
                         GEMM_SMEM_BYTES);

    k_zero<<<256, 256>>>();
    k_stats<<<512, 256>>>(x);
    k_bnfin<<<1, 128>>>(gamma, beta);
    k_gemm<<<(NN + 127) / 128, 256, GEMM_SMEM_BYTES>>>(x, W, attS, attD);
    k_edge_s<<<(NE + 255) / 256, 256>>>(ei);
    k_sinv<<<(NN * NH + 255) / 256, 256>>>();
    k_edge_msg<<<(NE * 4 + 255) / 256, 256>>>(ei);
    k_node_final<<<(NN * 16 + 255) / 256, 256>>>(batch, bias);
    k_pool_div<<<(NG * NC + 255) / 256, 256>>>(out);
}

// round 5
// speedup vs baseline: 1.3788x; 1.0570x over previous
#include <cuda_runtime.h>
#include <cuda_bf16.h>
#include <math.h>

#define NN 100000
#define NE 1600000
#define NG 100
#define NH 8
#define NC 16
#define NF 128

// ---------------- scratch (static device globals) ---------------------------
__device__ __align__(16) __nv_bfloat16 g_hb[(size_t)NN * NF];  // 25.6 MB h (bf16)
__device__ __align__(16) float g_asrc[NN * NH];
__device__ __align__(16) float g_adst[NN * NH];
__device__ __align__(16) float g_s[NN * NH];           // softmax denom, then inverted
__device__ __align__(16) float g_acc[NN * NC];         // head-averaged message accum
__device__ __align__(16) float g_colsum[NF];
__device__ __align__(16) float g_colsq[NF];
__device__ __align__(16) float g_scale[NF];
__device__ __align__(16) float g_shift[NF];
__device__ __align__(16) float g_pool[NG * NC];
__device__ __align__(16) float g_cnt[NG];

// vector reduction (no return) --------------------------------------------
__device__ __forceinline__ void red_v4(float* p, float a, float b, float c, float d) {
    asm volatile("red.global.add.v4.f32 [%0], {%1, %2, %3, %4};"
                 :: "l"(p), "f"(a), "f"(b), "f"(c), "f"(d) : "memory");
}

// ---------------- K0: zero accumulators ------------------------------------
__global__ void k_zero() {
    int i = blockIdx.x * blockDim.x + threadIdx.x;
    int st = gridDim.x * blockDim.x;
    for (int k = i; k < NN * NC; k += st) g_acc[k] = 0.f;
    if (i < NF) { g_colsum[i] = 0.f; g_colsq[i] = 0.f; }
    if (i < NG * NC) g_pool[i] = 0.f;
    if (i < NG) g_cnt[i] = 0.f;
}

// ---------------- K1: BN column stats --------------------------------------
__global__ void k_stats(const float* __restrict__ x) {
    __shared__ float ssum[NF];
    __shared__ float ssq[NF];
    int t = threadIdx.x;
    int lane = t & 31;
    int warp = t >> 5;
    int col = lane * 4;
    if (t < NF) { ssum[t] = 0.f; ssq[t] = 0.f; }
    __syncthreads();

    float s0 = 0.f, s1 = 0.f, s2 = 0.f, s3 = 0.f;
    float q0 = 0.f, q1 = 0.f, q2 = 0.f, q3 = 0.f;
    int row = blockIdx.x * 8 + warp;
    int step = gridDim.x * 8;
    for (int r = row; r < NN; r += step) {
        float4 v = *(const float4*)(x + (size_t)r * NF + col);
        s0 += v.x; s1 += v.y; s2 += v.z; s3 += v.w;
        q0 += v.x * v.x; q1 += v.y * v.y; q2 += v.z * v.z; q3 += v.w * v.w;
    }
    atomicAdd(&ssum[col + 0], s0); atomicAdd(&ssum[col + 1], s1);
    atomicAdd(&ssum[col + 2], s2); atomicAdd(&ssum[col + 3], s3);
    atomicAdd(&ssq[col + 0], q0);  atomicAdd(&ssq[col + 1], q1);
    atomicAdd(&ssq[col + 2], q2);  atomicAdd(&ssq[col + 3], q3);
    __syncthreads();
    if (t < NF) {
        atomicAdd(&g_colsum[t], ssum[t]);
        atomicAdd(&g_colsq[t], ssq[t]);
    }
}

// ---------------- K2: finalize BN scale/shift ------------------------------
__global__ void k_bnfin(const float* __restrict__ gamma, const float* __restrict__ beta) {
    int t = threadIdx.x;
    if (t < NF) {
        float mean = g_colsum[t] * (1.f / NN);
        float var = g_colsq[t] * (1.f / NN) - mean * mean;
        float sc = gamma[t] * rsqrtf(var + 1e-5f);
        g_scale[t] = sc;
        g_shift[t] = beta[t] - mean * sc;
    }
}

// ---------------- K3: fused BN + GEMM + attention logits --------------------
// 128 nodes/block, 256 threads, 8x8 microtile, K chunked by 64 (2 CTAs/SM).
// Logits computed from fp32 registers; h stored to global as bf16.
#define KCH 64
#define SXT_STRIDE 132                           // 528 B/row = 33*16 (16B aligned)
#define SXT_FLOATS (KCH * SXT_STRIDE)
#define SW_FLOATS (KCH * 128)
#define GEMM_SMEM_BYTES ((SXT_FLOATS + SW_FLOATS) * 4)

__global__ void __launch_bounds__(256, 2)
k_gemm(const float* __restrict__ x, const float* __restrict__ W,
       const float* __restrict__ attS, const float* __restrict__ attD) {
    extern __shared__ float sm[];
    float* sxT = sm;                 // [k][row] stride 132
    float* sw = sm + SXT_FLOATS;     // [k][col]

    int t = threadIdx.x;
    int r0 = blockIdx.x * 128;
    int j = t & 15, i4 = t >> 4;

    float acc[8][8];
#pragma unroll
    for (int m = 0; m < 8; ++m)
#pragma unroll
        for (int n = 0; n < 8; ++n) acc[m][n] = 0.f;

    for (int k0 = 0; k0 < NF; k0 += KCH) {
        for (int i = t; i < SW_FLOATS / 4; i += 256)
            ((float4*)sw)[i] = ((const float4*)(W + (size_t)k0 * 128))[i];
        for (int i = t; i < 128 * KCH; i += 256) {
            int row = i >> 6, col = i & 63;
            int n = r0 + row;
            float v = 0.f;
            if (n < NN) v = x[(size_t)n * NF + k0 + col] * g_scale[k0 + col] + g_shift[k0 + col];
            sxT[col * SXT_STRIDE + row] = v;
        }
        __syncthreads();

        const float* aBase = sxT + i4 * 8;
        const float* bBase = sw + j * 8;
#pragma unroll 4
        for (int k = 0; k < KCH; ++k) {
            float4 a0 = *(const float4*)(aBase + k * SXT_STRIDE);
            float4 a1 = *(const float4*)(aBase + k * SXT_STRIDE + 4);
            float4 b0 = *(const float4*)(bBase + k * 128);
            float4 b1 = *(const float4*)(bBase + k * 128 + 4);
            float a[8] = {a0.x, a0.y, a0.z, a0.w, a1.x, a1.y, a1.z, a1.w};
            float b[8] = {b0.x, b0.y, b0.z, b0.w, b1.x, b1.y, b1.z, b1.w};
#pragma unroll
            for (int m = 0; m < 8; ++m)
#pragma unroll
                for (int n = 0; n < 8; ++n) acc[m][n] = fmaf(a[m], b[n], acc[m][n]);
        }
        __syncthreads();
    }

    int rowsValid = NN - r0;
    if (rowsValid > 128) rowsValid = 128;

    // store h tile as bf16 straight from registers (16B per thread per row)
#pragma unroll
    for (int m = 0; m < 8; ++m) {
        int row = i4 * 8 + m;
        if (row < rowsValid) {
            __nv_bfloat162 p[4];
#pragma unroll
            for (int c = 0; c < 4; ++c)
                p[c] = __float22bfloat162_rn(make_float2(acc[m][2 * c], acc[m][2 * c + 1]));
            *(uint4*)(g_hb + (size_t)(r0 + row) * NF + j * 8) = *(uint4*)p;
        }
    }

    // attention logits from fp32 regs: thread covers half of head hh=j>>1
    int hh = j >> 1;
    float asv[8], adv[8];
#pragma unroll
    for (int c = 0; c < 8; ++c) {
        asv[c] = attS[hh * 16 + (j & 1) * 8 + c];
        adv[c] = attD[hh * 16 + (j & 1) * 8 + c];
    }
#pragma unroll
    for (int m = 0; m < 8; ++m) {
        float ps = 0.f, pd = 0.f;
#pragma unroll
        for (int c = 0; c < 8; ++c) {
            ps = fmaf(acc[m][c], asv[c], ps);
            pd = fmaf(acc[m][c], adv[c], pd);
        }
        ps += __shfl_xor_sync(0xffffffffu, ps, 1);
        pd += __shfl_xor_sync(0xffffffffu, pd, 1);
        int row = i4 * 8 + m;
        if ((j & 1) == 0 && row < rowsValid) {
            int n = r0 + row;
            g_asrc[n * NH + hh] = ps;
            g_adst[n * NH + hh] = pd;
            float e = ps + pd;
            e = e > 0.f ? e : 0.2f * e;
            g_s[n * NH + hh] = __expf(e);   // self-loop contribution
        }
    }
}

// ---------------- K4: edge pass 1 — softmax denominators -------------------
__device__ __forceinline__ float lrelu_exp(float a, float b) {
    float e = a + b;
    e = e > 0.f ? e : 0.2f * e;
    return __expf(e);
}

__global__ void k_edge_s(const int* __restrict__ ei) {
    int e = blockIdx.x * blockDim.x + threadIdx.x;
    if (e >= NE) return;
    int s = ei[e];
    int d = ei[NE + e];
    float4 a0 = *(const float4*)(g_asrc + s * NH);
    float4 a1 = *(const float4*)(g_asrc + s * NH + 4);
    float4 b0 = *(const float4*)(g_adst + d * NH);
    float4 b1 = *(const float4*)(g_adst + d * NH + 4);
    float* sp = g_s + d * NH;
    red_v4(sp, lrelu_exp(a0.x, b0.x), lrelu_exp(a0.y, b0.y),
               lrelu_exp(a0.z, b0.z), lrelu_exp(a0.w, b0.w));
    red_v4(sp + 4, lrelu_exp(a1.x, b1.x), lrelu_exp(a1.y, b1.y),
                   lrelu_exp(a1.z, b1.z), lrelu_exp(a1.w, b1.w));
}

// ---------------- K4b: invert denominators ---------------------------------
__global__ void k_sinv() {
    int i = blockIdx.x * blockDim.x + threadIdx.x;
    if (i < NN * NH) g_s[i] = __frcp_rn(g_s[i]);
}

// ---------------- K5: edge pass 2 — head-averaged message scatter ----------
// 4 threads per edge; lane q handles channels [4q, 4q+4). h gathered as bf16.
__global__ void k_edge_msg(const int* __restrict__ ei) {
    int gt = blockIdx.x * blockDim.x + threadIdx.x;
    int e = gt >> 2, q = gt & 3;
    if (e >= NE) return;
    int s = ei[e];
    int d = ei[NE + e];
    float4 a0 = *(const float4*)(g_asrc + s * NH);
    float4 a1 = *(const float4*)(g_asrc + s * NH + 4);
    float4 b0 = *(const float4*)(g_adst + d * NH);
    float4 b1 = *(const float4*)(g_adst + d * NH + 4);
    float4 s0 = *(const float4*)(g_s + d * NH);
    float4 s1 = *(const float4*)(g_s + d * NH + 4);
    float al[8];
    al[0] = 0.125f * lrelu_exp(a0.x, b0.x) * s0.x;
    al[1] = 0.125f * lrelu_exp(a0.y, b0.y) * s0.y;
    al[2] = 0.125f * lrelu_exp(a0.z, b0.z) * s0.z;
    al[3] = 0.125f * lrelu_exp(a0.w, b0.w) * s0.w;
    al[4] = 0.125f * lrelu_exp(a1.x, b1.x) * s1.x;
    al[5] = 0.125f * lrelu_exp(a1.y, b1.y) * s1.y;
    al[6] = 0.125f * lrelu_exp(a1.z, b1.z) * s1.z;
    al[7] = 0.125f * lrelu_exp(a1.w, b1.w) * s1.w;

    const __nv_bfloat16* hrow = g_hb + (size_t)s * NF + q * 4;
    float r0 = 0.f, r1 = 0.f, r2 = 0.f, r3 = 0.f;
#pragma unroll
    for (int h = 0; h < NH; ++h) {
        // 4 bf16 = 8 bytes, 8B-aligned (s*256 + q*8 + h*32)
        __nv_bfloat162 p01 = *(const __nv_bfloat162*)(hrow + h * 16);
        __nv_bfloat162 p23 = *(const __nv_bfloat162*)(hrow + h * 16 + 2);
        float2 f01 = __bfloat1622float2(p01);
        float2 f23 = __bfloat1622float2(p23);
        r0 = fmaf(al[h], f01.x, r0);
        r1 = fmaf(al[h], f01.y, r1);
        r2 = fmaf(al[h], f23.x, r2);
        r3 = fmaf(al[h], f23.y, r3);
    }
    red_v4(g_acc + d * NC + q * 4, r0, r1, r2, r3);
}

// ---------------- K6: node finalize (self-loop + bias + ELU + pool) --------
__global__ void k_node_final(const int* __restrict__ batch,
                             const float* __restrict__ bias) {
    int gt = blockIdx.x * blockDim.x + threadIdx.x;
    int n = gt >> 4, c = gt & 15;
    if (n >= NN) return;
    float v = g_acc[n * NC + c];
    const __nv_bfloat16* hr = g_hb + (size_t)n * NF;
#pragma unroll
    for (int h = 0; h < NH; ++h) {
        float a = g_asrc[n * NH + h] + g_adst[n * NH + h];
        a = a > 0.f ? a : 0.2f * a;
        float w = __expf(a) * g_s[n * NH + h];   // g_s holds 1/s
        v = fmaf(0.125f * w, __bfloat162float(hr[h * 16 + c]), v);
    }
    v += bias[c];
    v = v > 0.f ? v : expm1f(v);
    int b = batch[n];
    atomicAdd(&g_pool[b * NC + c], v);
    if (c == 0) atomicAdd(&g_cnt[b], 1.0f);
}

// ---------------- K7: pooled mean ------------------------------------------
__global__ void k_pool_div(float* __restrict__ out) {
    int i = blockIdx.x * blockDim.x + threadIdx.x;
    if (i < NG * NC) {
        int g = i >> 4;
        out[i] = g_pool[i] / fmaxf(g_cnt[g], 1.0f);
    }
}

// ---------------- launch ----------------------------------------------------
extern "C" void kernel_launch(void* const* d_in, const int* in_sizes, int n_in,
                              void* d_out, int out_size) {
    const float* x = (const float*)d_in[0];
    const int* ei = (const int*)d_in[1];
    const int* batch = (const int*)d_in[2];
    const float* gamma = (const float*)d_in[3];
    const float* beta = (const float*)d_in[4];
    const float* W = (const float*)d_in[5];
    const float* attS = (const float*)d_in[6];
    const float* attD = (const float*)d_in[7];
    const float* bias = (const float*)d_in[8];
    float* out = (float*)d_out;

    cudaFuncSetAttribute(k_gemm, cudaFuncAttributeMaxDynamicSharedMemorySize,
                         GEMM_SMEM_BYTES);

    k_zero<<<256, 256>>>();
    k_stats<<<512, 256>>>(x);
    k_bnfin<<<1, 128>>>(gamma, beta);
    k_gemm<<<(NN + 127) / 128, 256, GEMM_SMEM_BYTES>>>(x, W, attS, attD);
    k_edge_s<<<(NE + 255) / 256, 256>>>(ei);
    k_sinv<<<(NN * NH + 255) / 256, 256>>>();
    k_edge_msg<<<(NE * 4 + 255) / 256, 256>>>(ei);
    k_node_final<<<(NN * 16 + 255) / 256, 256>>>(batch, bias);
    k_pool_div<<<(NG * NC + 255) / 256, 256>>>(out);
}